// round 3
// baseline (speedup 1.0000x reference)
#include <cuda_runtime.h>
#include <cuda_bf16.h>
#include <cstdint>

// ----------------------------------------------------------------------------
// GCN: 5x (GCNConv + ReLU) + global mean pool + linear head.
//   Fixed shapes: N=100000, E=1600000, H=128, C=10, L=5, G=64
// Strategy:
//   - Build CSR over dst once per launch (self-loops included), norm = dis[s]*dis[d]
//   - Per layer: agg = A_norm * x   (warp-per-row CSR SpMM, no atomics)
//                x   = relu(agg @ W + b)  (fp32 GEMM using packed fma.rn.f32x2)
//   - Mean-pool per graph (batch is sorted -> binary-search boundaries)
//   - Tiny output GEMM  pooled @ W_out + b_out
// ----------------------------------------------------------------------------

#define MAXN 100352
#define MAXT 1703936      // >= E + N
#define MAXG 1024
#define HH   128

__device__ int   g_cnt[MAXN];
__device__ float g_dis[MAXN];
__device__ int   g_rowptr[MAXN + 1];
__device__ int   g_cursor[MAXN];
__device__ int2  g_edges[MAXT];
__device__ float g_agg[(size_t)MAXN * HH];
__device__ float g_x1 [(size_t)MAXN * HH];
__device__ float g_x2 [(size_t)MAXN * HH];
__device__ int   g_bsum[256];
__device__ int   g_gstart[MAXG + 1];
__device__ float g_pooled[(size_t)MAXG * HH];

// ---------------------------- packed f32x2 helpers --------------------------
__device__ __forceinline__ unsigned long long pack2(float x) {
    unsigned long long r;
    asm("mov.b64 %0, {%1, %1};" : "=l"(r) : "f"(x));
    return r;
}
__device__ __forceinline__ void ffma2(unsigned long long& d,
                                      unsigned long long a,
                                      unsigned long long b) {
    asm("fma.rn.f32x2 %0, %1, %2, %0;" : "+l"(d) : "l"(a), "l"(b));
}
__device__ __forceinline__ float2 unpack2(unsigned long long v) {
    float2 f;
    asm("mov.b64 {%0, %1}, %2;" : "=f"(f.x), "=f"(f.y) : "l"(v));
    return f;
}

// ------------------------------- graph prep ---------------------------------
__global__ void k_init(int* cnt, int n) {
    int i = blockIdx.x * blockDim.x + threadIdx.x;
    if (i < n) cnt[i] = 1;  // self loop
}

__global__ void k_count(const int* __restrict__ dst, int* cnt, int e) {
    int i = blockIdx.x * blockDim.x + threadIdx.x;
    if (i < e) atomicAdd(&cnt[dst[i]], 1);
}

__global__ void k_dis(const int* __restrict__ cnt, float* dis, int n) {
    int i = blockIdx.x * blockDim.x + threadIdx.x;
    if (i < n) dis[i] = rsqrtf((float)cnt[i]);  // cnt >= 1 always
}

// block of 256 threads handles 1024 counts -> partial sum
__global__ void k_scan1(const int* __restrict__ cnt, int* bsum, int n) {
    __shared__ int sh[256];
    int t = threadIdx.x;
    int base = blockIdx.x * 1024 + t * 4;
    int s = 0;
#pragma unroll
    for (int i = 0; i < 4; i++)
        if (base + i < n) s += cnt[base + i];
    sh[t] = s;
    __syncthreads();
#pragma unroll
    for (int off = 128; off > 0; off >>= 1) {
        if (t < off) sh[t] += sh[t + off];
        __syncthreads();
    }
    if (t == 0) bsum[blockIdx.x] = sh[0];
}

// single block: exclusive scan of block sums (nb <= 256); writes rowptr[N]
__global__ void k_scan2(int* bsum, int* rowptr, int nb, int n) {
    __shared__ int sh[256];
    int t = threadIdx.x;
    sh[t] = (t < nb) ? bsum[t] : 0;
    __syncthreads();
    for (int off = 1; off < 256; off <<= 1) {
        int v = (t >= off) ? sh[t - off] : 0;
        __syncthreads();
        sh[t] += v;
        __syncthreads();
    }
    if (t < nb) bsum[t] = (t == 0) ? 0 : sh[t - 1];
    if (t == 0) rowptr[n] = sh[nb - 1];
}

__global__ void k_scan3(const int* __restrict__ cnt, const int* __restrict__ bsumex,
                        int* rowptr, int* cursor, int n) {
    __shared__ int sh[256];
    int t = threadIdx.x;
    int base = blockIdx.x * 1024 + t * 4;
    int v0 = 0, v1 = 0, v2 = 0, v3 = 0;
    if (base + 0 < n) v0 = cnt[base + 0];
    if (base + 1 < n) v1 = cnt[base + 1];
    if (base + 2 < n) v2 = cnt[base + 2];
    if (base + 3 < n) v3 = cnt[base + 3];
    int s = v0 + v1 + v2 + v3;
    sh[t] = s;
    __syncthreads();
    for (int off = 1; off < 256; off <<= 1) {
        int v = (t >= off) ? sh[t - off] : 0;
        __syncthreads();
        sh[t] += v;
        __syncthreads();
    }
    int ex = (t == 0) ? 0 : sh[t - 1];
    int off0 = bsumex[blockIdx.x] + ex;
    if (base + 0 < n) { rowptr[base + 0] = off0;                cursor[base + 0] = off0; }
    if (base + 1 < n) { rowptr[base + 1] = off0 + v0;           cursor[base + 1] = off0 + v0; }
    if (base + 2 < n) { rowptr[base + 2] = off0 + v0 + v1;      cursor[base + 2] = off0 + v0 + v1; }
    if (base + 3 < n) { rowptr[base + 3] = off0 + v0 + v1 + v2; cursor[base + 3] = off0 + v0 + v1 + v2; }
}

__global__ void k_fill(const int* __restrict__ src, const int* __restrict__ dst,
                       const float* __restrict__ dis, int* cursor, int2* edges,
                       int e, int n) {
    int i = blockIdx.x * blockDim.x + threadIdx.x;
    if (i >= e + n) return;
    int s, d;
    if (i < e) { s = src[i]; d = dst[i]; }
    else       { s = d = i - e; }
    float w = dis[s] * dis[d];
    int pos = atomicAdd(&cursor[d], 1);
    edges[pos] = make_int2(s, __float_as_int(w));
}

// --------------------------------- SpMM -------------------------------------
// warp per destination row, lane handles a float4 (H=128 = 32 lanes * 4)
__global__ void k_spmm(const int* __restrict__ rowptr, const int2* __restrict__ edges,
                       const float* __restrict__ xin, float* __restrict__ xout, int n) {
    int row  = (blockIdx.x * blockDim.x + threadIdx.x) >> 5;
    int lane = threadIdx.x & 31;
    if (row >= n) return;
    int s = rowptr[row], e = rowptr[row + 1];
    const float4* x4 = (const float4*)xin;
    float4 acc = make_float4(0.f, 0.f, 0.f, 0.f);
    int j = s;
    for (; j + 4 <= e; j += 4) {
        int2 e0 = __ldg(&edges[j + 0]);
        int2 e1 = __ldg(&edges[j + 1]);
        int2 e2 = __ldg(&edges[j + 2]);
        int2 e3 = __ldg(&edges[j + 3]);
        float4 v0 = __ldg(&x4[(size_t)e0.x * 32 + lane]);
        float4 v1 = __ldg(&x4[(size_t)e1.x * 32 + lane]);
        float4 v2 = __ldg(&x4[(size_t)e2.x * 32 + lane]);
        float4 v3 = __ldg(&x4[(size_t)e3.x * 32 + lane]);
        float w0 = __int_as_float(e0.y), w1 = __int_as_float(e1.y);
        float w2 = __int_as_float(e2.y), w3 = __int_as_float(e3.y);
        acc.x += w0 * v0.x; acc.y += w0 * v0.y; acc.z += w0 * v0.z; acc.w += w0 * v0.w;
        acc.x += w1 * v1.x; acc.y += w1 * v1.y; acc.z += w1 * v1.z; acc.w += w1 * v1.w;
        acc.x += w2 * v2.x; acc.y += w2 * v2.y; acc.z += w2 * v2.z; acc.w += w2 * v2.w;
        acc.x += w3 * v3.x; acc.y += w3 * v3.y; acc.z += w3 * v3.z; acc.w += w3 * v3.w;
    }
    for (; j < e; j++) {
        int2 ed = __ldg(&edges[j]);
        float w = __int_as_float(ed.y);
        float4 v = __ldg(&x4[(size_t)ed.x * 32 + lane]);
        acc.x += w * v.x; acc.y += w * v.y; acc.z += w * v.z; acc.w += w * v.w;
    }
    ((float4*)xout)[(size_t)row * 32 + lane] = acc;
}

// --------------------------------- GEMM -------------------------------------
// out[m][n] = relu( sum_k A[m][k]*W[k][n] + bias[n] ), M tile = 128, K = N = 128
// 256 threads, each computes 8 rows x 8 cols via packed fma.rn.f32x2 (FFMA2).
#define SA 132  // padded stride for transposed A tile (conflict-free)
#define SMEM_GEMM ((HH * SA + HH * HH) * 4)

__global__ __launch_bounds__(256, 1)
void k_gemm(const float* __restrict__ A, const float* __restrict__ W,
            const float* __restrict__ bias, float* __restrict__ out, int n) {
    extern __shared__ float sh[];
    float* AsT = sh;              // [k][m], stride SA
    float* Wsh = sh + HH * SA;    // [k][n], stride 128
    const int tid = threadIdx.x;
    const int m0 = blockIdx.x * 128;

    // stage W (row-major copy)
    for (int i = tid * 4; i < HH * HH; i += 1024)
        *(float4*)&Wsh[i] = *(const float4*)&W[i];

    // stage A transposed: A[r][k] -> AsT[k][r]
    for (int idx = tid; idx < 128 * 32; idx += 256) {
        int row = idx >> 5;
        int kq  = idx & 31;
        float4 v = make_float4(0.f, 0.f, 0.f, 0.f);
        int r = m0 + row;
        if (r < n) v = *(const float4*)&A[(size_t)r * HH + kq * 4];
        int k0 = kq * 4;
        AsT[(k0 + 0) * SA + row] = v.x;
        AsT[(k0 + 1) * SA + row] = v.y;
        AsT[(k0 + 2) * SA + row] = v.z;
        AsT[(k0 + 3) * SA + row] = v.w;
    }
    __syncthreads();

    const int tn = tid & 15, tm = tid >> 4;
    const int nA = tn * 4;   // cols nA..nA+3 and nA+64..nA+67
    const int mA = tm * 4;   // rows mA..mA+3 and mA+64..mA+67

    unsigned long long acc[8][4];
#pragma unroll
    for (int r = 0; r < 8; r++)
#pragma unroll
        for (int p = 0; p < 4; p++) acc[r][p] = 0ull;

#pragma unroll 4
    for (int k = 0; k < 128; k++) {
        const float4 a0 = *(const float4*)&AsT[k * SA + mA];
        const float4 a1 = *(const float4*)&AsT[k * SA + mA + 64];
        const ulonglong2 q0 = *(const ulonglong2*)&Wsh[k * 128 + nA];
        const ulonglong2 q1 = *(const ulonglong2*)&Wsh[k * 128 + nA + 64];
        float av[8] = {a0.x, a0.y, a0.z, a0.w, a1.x, a1.y, a1.z, a1.w};
#pragma unroll
        for (int r = 0; r < 8; r++) {
            unsigned long long ap = pack2(av[r]);
            ffma2(acc[r][0], ap, q0.x);
            ffma2(acc[r][1], ap, q0.y);
            ffma2(acc[r][2], ap, q1.x);
            ffma2(acc[r][3], ap, q1.y);
        }
    }

    float bn[8];
#pragma unroll
    for (int i = 0; i < 4; i++) {
        bn[i]     = bias[nA + i];
        bn[i + 4] = bias[nA + 64 + i];
    }

#pragma unroll
    for (int r = 0; r < 8; r++) {
        int m = m0 + mA + ((r < 4) ? r : (64 + r - 4));
        if (m < n) {
            float2 u0 = unpack2(acc[r][0]);
            float2 u1 = unpack2(acc[r][1]);
            float2 u2 = unpack2(acc[r][2]);
            float2 u3 = unpack2(acc[r][3]);
            float4 w0 = make_float4(fmaxf(u0.x + bn[0], 0.f), fmaxf(u0.y + bn[1], 0.f),
                                    fmaxf(u1.x + bn[2], 0.f), fmaxf(u1.y + bn[3], 0.f));
            float4 w1 = make_float4(fmaxf(u2.x + bn[4], 0.f), fmaxf(u2.y + bn[5], 0.f),
                                    fmaxf(u3.x + bn[6], 0.f), fmaxf(u3.y + bn[7], 0.f));
            *(float4*)&out[(size_t)m * HH + nA]      = w0;
            *(float4*)&out[(size_t)m * HH + nA + 64] = w1;
        }
    }
}

// ------------------------------ pooling / head ------------------------------
__global__ void k_gbounds(const int* __restrict__ batch, int* gstart, int n, int g_num) {
    int g = blockIdx.x * blockDim.x + threadIdx.x;
    if (g > g_num) return;
    int lo = 0, hi = n;
    while (lo < hi) {
        int mid = (lo + hi) >> 1;
        if (batch[mid] < g) lo = mid + 1; else hi = mid;
    }
    gstart[g] = lo;
}

__global__ void k_pool(const float* __restrict__ x, const int* __restrict__ gstart,
                       float* __restrict__ pooled) {
    int g = blockIdx.x, t = threadIdx.x;
    int s = gstart[g], e = gstart[g + 1];
    float acc = 0.f;
    int r = s;
    for (; r + 4 <= e; r += 4) {
        acc += x[(size_t)(r + 0) * HH + t];
        acc += x[(size_t)(r + 1) * HH + t];
        acc += x[(size_t)(r + 2) * HH + t];
        acc += x[(size_t)(r + 3) * HH + t];
    }
    for (; r < e; r++) acc += x[(size_t)r * HH + t];
    float c = (float)(e - s);
    pooled[(size_t)g * HH + t] = acc / fmaxf(c, 1.0f);
}

__global__ void k_out(const float* __restrict__ pooled, const float* __restrict__ Wout,
                      const float* __restrict__ bout, float* __restrict__ out, int C) {
    __shared__ float pr[HH];
    int g = blockIdx.x, t = threadIdx.x;
    pr[t] = pooled[(size_t)g * HH + t];
    __syncthreads();
    if (t < C) {
        float s = bout[t];
#pragma unroll 8
        for (int k = 0; k < HH; k++) s += pr[k] * Wout[k * C + t];
        out[g * C + t] = s;
    }
}

// --------------------------------- launch -----------------------------------
extern "C" void kernel_launch(void* const* d_in, const int* in_sizes, int n_in,
                              void* d_out, int out_size) {
    const float* x     = (const float*)d_in[0];
    const int*   ei    = (const int*)d_in[1];
    const int*   batch = (const int*)d_in[2];
    int iw, ibs, iwo, ibo;
    if (n_in >= 8) { iw = 4; ibs = 5; iwo = 6; ibo = 7; }  // num_graphs at index 3
    else           { iw = 3; ibs = 4; iwo = 5; ibo = 6; }
    const float* Ws   = (const float*)d_in[iw];
    const float* bs   = (const float*)d_in[ibs];
    const float* Wout = (const float*)d_in[iwo];
    const float* bout = (const float*)d_in[ibo];

    int N = in_sizes[2];
    int E = in_sizes[1] / 2;
    int H = in_sizes[0] / N;            // expect 128
    int C = in_sizes[ibo];
    int L = in_sizes[ibs] / H;
    int G = out_size / C;
    if (N > MAXN || (E + N) > MAXT || G > MAXG || H != HH) return;

    void* p;
    cudaGetSymbolAddress(&p, g_cnt);     int*   cnt    = (int*)p;
    cudaGetSymbolAddress(&p, g_dis);     float* dis    = (float*)p;
    cudaGetSymbolAddress(&p, g_rowptr);  int*   rowptr = (int*)p;
    cudaGetSymbolAddress(&p, g_cursor);  int*   cursor = (int*)p;
    cudaGetSymbolAddress(&p, g_edges);   int2*  edges  = (int2*)p;
    cudaGetSymbolAddress(&p, g_agg);     float* agg    = (float*)p;
    cudaGetSymbolAddress(&p, g_x1);      float* x1     = (float*)p;
    cudaGetSymbolAddress(&p, g_x2);      float* x2     = (float*)p;
    cudaGetSymbolAddress(&p, g_bsum);    int*   bsum   = (int*)p;
    cudaGetSymbolAddress(&p, g_gstart);  int*   gstart = (int*)p;
    cudaGetSymbolAddress(&p, g_pooled);  float* pooled = (float*)p;

    cudaFuncSetAttribute(k_gemm, cudaFuncAttributeMaxDynamicSharedMemorySize, SMEM_GEMM);

    const int* src = ei;
    const int* dst = ei + E;

    k_init <<<(N + 255) / 256, 256>>>(cnt, N);
    k_count<<<(E + 255) / 256, 256>>>(dst, cnt, E);
    k_dis  <<<(N + 255) / 256, 256>>>(cnt, dis, N);

    int NB = (N + 1023) / 1024;
    k_scan1<<<NB, 256>>>(cnt, bsum, N);
    k_scan2<<<1, 256>>>(bsum, rowptr, NB, N);
    k_scan3<<<NB, 256>>>(cnt, bsum, rowptr, cursor, N);
    k_fill <<<(E + N + 255) / 256, 256>>>(src, dst, dis, cursor, edges, E, N);

    const float* xin = x;
    for (int l = 0; l < L; l++) {
        k_spmm<<<(N + 7) / 8, 256>>>(rowptr, edges, xin, agg, N);
        float* xout = (l & 1) ? x2 : x1;
        k_gemm<<<(N + 127) / 128, 256, SMEM_GEMM>>>(agg, Ws + (size_t)l * H * H,
                                                    bs + (size_t)l * H, xout, N);
        xin = xout;
    }

    k_gbounds<<<(G + 1 + 127) / 128, 128>>>(batch, gstart, N, G);
    k_pool<<<G, HH>>>(xin, gstart, pooled);
    k_out <<<G, HH>>>(pooled, Wout, bout, (float*)d_out, C);
}

// round 7
// speedup vs baseline: 1.3345x; 1.3345x over previous
#include <cuda_runtime.h>
#include <cuda_bf16.h>
#include <cstdint>

// ----------------------------------------------------------------------------
// GCN: 5x (GCNConv + ReLU) + global mean pool + linear head.
//   Fixed shapes: N=100000, E=1600000, H=128, C=10, L=5, G=64
//   - CSR build over dst (self-loops included), norm = dis[s]*dis[d]
//   - Per layer: agg = A_norm * x   (warp-per-row CSR SpMM, no atomics)
//                x   = relu(agg @ W + b)  via tensor-core tf32 mma with
//                3-term error-compensated split (hi=tf32, lo=bf16) -> ~fp32 acc.
//   - Mean-pool per graph (batch sorted -> binary-search boundaries)
// ----------------------------------------------------------------------------

#define MAXN 100352
#define MAXT 1703936      // >= E + N
#define MAXG 1024
#define HH   128

__device__ int   g_cnt[MAXN];
__device__ float g_dis[MAXN];
__device__ int   g_rowptr[MAXN + 1];
__device__ int   g_cursor[MAXN];
__device__ int2  g_edges[MAXT];
__device__ float g_agg[(size_t)MAXN * HH];
__device__ float g_x1 [(size_t)MAXN * HH];
__device__ float g_x2 [(size_t)MAXN * HH];
__device__ int   g_bsum[256];
__device__ int   g_gstart[MAXG + 1];
__device__ float g_pooled[(size_t)MAXG * HH];

// ------------------------------- graph prep ---------------------------------
__global__ void k_init(int* cnt, int n) {
    int i = blockIdx.x * blockDim.x + threadIdx.x;
    if (i < n) cnt[i] = 1;  // self loop
}

__global__ void k_count(const int* __restrict__ dst, int* cnt, int e) {
    int i = blockIdx.x * blockDim.x + threadIdx.x;
    if (i < e) atomicAdd(&cnt[dst[i]], 1);
}

__global__ void k_dis(const int* __restrict__ cnt, float* dis, int n) {
    int i = blockIdx.x * blockDim.x + threadIdx.x;
    if (i < n) dis[i] = rsqrtf((float)cnt[i]);  // cnt >= 1 always
}

__global__ void k_scan1(const int* __restrict__ cnt, int* bsum, int n) {
    __shared__ int sh[256];
    int t = threadIdx.x;
    int base = blockIdx.x * 1024 + t * 4;
    int s = 0;
#pragma unroll
    for (int i = 0; i < 4; i++)
        if (base + i < n) s += cnt[base + i];
    sh[t] = s;
    __syncthreads();
#pragma unroll
    for (int off = 128; off > 0; off >>= 1) {
        if (t < off) sh[t] += sh[t + off];
        __syncthreads();
    }
    if (t == 0) bsum[blockIdx.x] = sh[0];
}

__global__ void k_scan2(int* bsum, int* rowptr, int nb, int n) {
    __shared__ int sh[256];
    int t = threadIdx.x;
    sh[t] = (t < nb) ? bsum[t] : 0;
    __syncthreads();
    for (int off = 1; off < 256; off <<= 1) {
        int v = (t >= off) ? sh[t - off] : 0;
        __syncthreads();
        sh[t] += v;
        __syncthreads();
    }
    if (t < nb) bsum[t] = (t == 0) ? 0 : sh[t - 1];
    if (t == 0) rowptr[n] = sh[nb - 1];
}

__global__ void k_scan3(const int* __restrict__ cnt, const int* __restrict__ bsumex,
                        int* rowptr, int* cursor, int n) {
    __shared__ int sh[256];
    int t = threadIdx.x;
    int base = blockIdx.x * 1024 + t * 4;
    int v0 = 0, v1 = 0, v2 = 0, v3 = 0;
    if (base + 0 < n) v0 = cnt[base + 0];
    if (base + 1 < n) v1 = cnt[base + 1];
    if (base + 2 < n) v2 = cnt[base + 2];
    if (base + 3 < n) v3 = cnt[base + 3];
    int s = v0 + v1 + v2 + v3;
    sh[t] = s;
    __syncthreads();
    for (int off = 1; off < 256; off <<= 1) {
        int v = (t >= off) ? sh[t - off] : 0;
        __syncthreads();
        sh[t] += v;
        __syncthreads();
    }
    int ex = (t == 0) ? 0 : sh[t - 1];
    int off0 = bsumex[blockIdx.x] + ex;
    if (base + 0 < n) { rowptr[base + 0] = off0;                cursor[base + 0] = off0; }
    if (base + 1 < n) { rowptr[base + 1] = off0 + v0;           cursor[base + 1] = off0 + v0; }
    if (base + 2 < n) { rowptr[base + 2] = off0 + v0 + v1;      cursor[base + 2] = off0 + v0 + v1; }
    if (base + 3 < n) { rowptr[base + 3] = off0 + v0 + v1 + v2; cursor[base + 3] = off0 + v0 + v1 + v2; }
}

__global__ void k_fill(const int* __restrict__ src, const int* __restrict__ dst,
                       const float* __restrict__ dis, int* cursor, int2* edges,
                       int e, int n) {
    int i = blockIdx.x * blockDim.x + threadIdx.x;
    if (i >= e + n) return;
    int s, d;
    if (i < e) { s = src[i]; d = dst[i]; }
    else       { s = d = i - e; }
    float w = dis[s] * dis[d];
    int pos = atomicAdd(&cursor[d], 1);
    edges[pos] = make_int2(s, __float_as_int(w));
}

// --------------------------------- SpMM -------------------------------------
__global__ void k_spmm(const int* __restrict__ rowptr, const int2* __restrict__ edges,
                       const float* __restrict__ xin, float* __restrict__ xout, int n) {
    int row  = (blockIdx.x * blockDim.x + threadIdx.x) >> 5;
    int lane = threadIdx.x & 31;
    if (row >= n) return;
    int s = rowptr[row], e = rowptr[row + 1];
    const float4* x4 = (const float4*)xin;
    float4 acc = make_float4(0.f, 0.f, 0.f, 0.f);
    int j = s;
    for (; j + 4 <= e; j += 4) {
        int2 e0 = __ldg(&edges[j + 0]);
        int2 e1 = __ldg(&edges[j + 1]);
        int2 e2 = __ldg(&edges[j + 2]);
        int2 e3 = __ldg(&edges[j + 3]);
        float4 v0 = __ldg(&x4[(size_t)e0.x * 32 + lane]);
        float4 v1 = __ldg(&x4[(size_t)e1.x * 32 + lane]);
        float4 v2 = __ldg(&x4[(size_t)e2.x * 32 + lane]);
        float4 v3 = __ldg(&x4[(size_t)e3.x * 32 + lane]);
        float w0 = __int_as_float(e0.y), w1 = __int_as_float(e1.y);
        float w2 = __int_as_float(e2.y), w3 = __int_as_float(e3.y);
        acc.x += w0 * v0.x; acc.y += w0 * v0.y; acc.z += w0 * v0.z; acc.w += w0 * v0.w;
        acc.x += w1 * v1.x; acc.y += w1 * v1.y; acc.z += w1 * v1.z; acc.w += w1 * v1.w;
        acc.x += w2 * v2.x; acc.y += w2 * v2.y; acc.z += w2 * v2.z; acc.w += w2 * v2.w;
        acc.x += w3 * v3.x; acc.y += w3 * v3.y; acc.z += w3 * v3.z; acc.w += w3 * v3.w;
    }
    for (; j < e; j++) {
        int2 ed = __ldg(&edges[j]);
        float w = __int_as_float(ed.y);
        float4 v = __ldg(&x4[(size_t)ed.x * 32 + lane]);
        acc.x += w * v.x; acc.y += w * v.y; acc.z += w * v.z; acc.w += w * v.w;
    }
    ((float4*)xout)[(size_t)row * 32 + lane] = acc;
}

// ------------------------- tensor-core GEMM helpers --------------------------
__device__ __forceinline__ uint32_t f2tf32(float v) {
    uint32_t u;
    asm("cvt.rna.tf32.f32 %0, %1;" : "=r"(u) : "f"(v));
    return u;
}
// pack two residuals as bf16x2; e0 -> lower half, e1 -> upper half
__device__ __forceinline__ uint32_t packbf(float e0, float e1) {
    uint32_t r;
    asm("cvt.rn.bf16x2.f32 %0, %1, %2;" : "=r"(r) : "f"(e1), "f"(e0));
    return r;
}
__device__ __forceinline__ void mma8(float* c,
                                     uint32_t a0, uint32_t a1, uint32_t a2, uint32_t a3,
                                     uint32_t b0, uint32_t b1) {
    asm volatile(
        "mma.sync.aligned.m16n8k8.row.col.f32.tf32.tf32.f32 "
        "{%0,%1,%2,%3}, {%4,%5,%6,%7}, {%8,%9}, {%0,%1,%2,%3};"
        : "+f"(c[0]), "+f"(c[1]), "+f"(c[2]), "+f"(c[3])
        : "r"(a0), "r"(a1), "r"(a2), "r"(a3), "r"(b0), "r"(b1));
}

// --------------------------------- GEMM --------------------------------------
// out[m][c] = relu( sum_k A[m][k]*W[k][c] + bias[c] ), block tile 128x128, K=128
// Fragment-major shared staging:
//   Ah: 16ks x 8mt x 32lane x 4 x f32  (64KB)   tf32 hi parts of A
//   Al: same shape, bf16 residuals     (32KB)
//   Bh: 16ks x 16nt x 32lane x 2 x f32 (64KB)   tf32 hi parts of W
//   Bl: same shape, bf16 residuals     (32KB)
#define SMEM_GEMM 196608

__global__ __launch_bounds__(256, 1)
void k_gemm_tc(const float* __restrict__ A, const float* __restrict__ W,
               const float* __restrict__ bias, float* __restrict__ out, int n) {
    extern __shared__ char sh[];
    uint4* Ah = (uint4*)sh;                      // 4096 slots
    uint2* Al = (uint2*)(sh + 65536);            // 4096 slots
    uint2* Bh = (uint2*)(sh + 98304);            // 8192 slots
    uint32_t* Bl = (uint32_t*)(sh + 163840);     // 8192 slots

    const int tid  = threadIdx.x;
    const int lane = tid & 31;
    const int g = lane >> 2, t = lane & 3;
    const int m0 = blockIdx.x << 7;

    // ---- stage A fragments (each thread owns whole lane-slots -> vector STS) ----
#pragma unroll
    for (int i = 0; i < 16; i++) {
        int s    = tid + i * 256;      // slot id; (s & 31) == lane
        int tile = s >> 5;             // 0..127
        int mt = tile & 7, ks = tile >> 3;
        int mrow = m0 + mt * 16 + g;
        int col  = ks * 8 + t;
        float v0 = 0.f, v1 = 0.f, v2 = 0.f, v3 = 0.f;
        if (mrow < n) {
            v0 = __ldg(&A[(size_t)mrow * HH + col]);
            v2 = __ldg(&A[(size_t)mrow * HH + col + 4]);
        }
        if (mrow + 8 < n) {
            v1 = __ldg(&A[(size_t)(mrow + 8) * HH + col]);
            v3 = __ldg(&A[(size_t)(mrow + 8) * HH + col + 4]);
        }
        uint32_t h0 = f2tf32(v0), h1 = f2tf32(v1), h2 = f2tf32(v2), h3 = f2tf32(v3);
        float l0 = v0 - __uint_as_float(h0), l1 = v1 - __uint_as_float(h1);
        float l2 = v2 - __uint_as_float(h2), l3 = v3 - __uint_as_float(h3);
        Ah[s] = make_uint4(h0, h1, h2, h3);
        Al[s] = make_uint2(packbf(l0, l1), packbf(l2, l3));
    }
    // ---- stage W fragments ----
#pragma unroll
    for (int i = 0; i < 32; i++) {
        int s    = tid + i * 256;
        int tile = s >> 5;             // 0..255
        int nt = tile & 15, ks = tile >> 4;
        int row = ks * 8 + t, col = nt * 8 + g;
        float v0 = __ldg(&W[row * HH + col]);
        float v1 = __ldg(&W[(row + 4) * HH + col]);
        uint32_t h0 = f2tf32(v0), h1 = f2tf32(v1);
        float l0 = v0 - __uint_as_float(h0), l1 = v1 - __uint_as_float(h1);
        Bh[s] = make_uint2(h0, h1);
        Bl[s] = packbf(l0, l1);
    }
    __syncthreads();

    const int warp = tid >> 5;
    const int wm = warp >> 2;      // 0..1  (64 rows each)
    const int wn = warp & 3;       // 0..3  (32 cols each)

    float acc[4][4][4];
#pragma unroll
    for (int a = 0; a < 4; a++)
#pragma unroll
        for (int b = 0; b < 4; b++)
#pragma unroll
            for (int c = 0; c < 4; c++) acc[a][b][c] = 0.f;

#pragma unroll 2
    for (int ks = 0; ks < 16; ks++) {
        uint4 ah[4]; uint2 alp[4];
#pragma unroll
        for (int mt = 0; mt < 4; mt++) {
            int slot = (ks * 8 + wm * 4 + mt) * 32 + lane;
            ah[mt]  = Ah[slot];
            alp[mt] = Al[slot];
        }
        uint2 bh[4]; uint32_t blp[4];
#pragma unroll
        for (int nt = 0; nt < 4; nt++) {
            int slot = (ks * 16 + wn * 4 + nt) * 32 + lane;
            bh[nt]  = Bh[slot];
            blp[nt] = Bl[slot];
        }
#pragma unroll
        for (int mt = 0; mt < 4; mt++) {
            uint32_t a0 = ah[mt].x, a1 = ah[mt].y, a2 = ah[mt].z, a3 = ah[mt].w;
            uint32_t q0 = alp[mt].x << 16, q1 = alp[mt].x & 0xFFFF0000u;
            uint32_t q2 = alp[mt].y << 16, q3 = alp[mt].y & 0xFFFF0000u;
#pragma unroll
            for (int nt = 0; nt < 4; nt++) {
                uint32_t b0 = bh[nt].x, b1 = bh[nt].y;
                uint32_t r0 = blp[nt] << 16, r1 = blp[nt] & 0xFFFF0000u;
                mma8(acc[mt][nt], a0, a1, a2, a3, b0, b1);   // hi*hi
                mma8(acc[mt][nt], a0, a1, a2, a3, r0, r1);   // hi*lo
                mma8(acc[mt][nt], q0, q1, q2, q3, b0, b1);   // lo*hi
            }
        }
    }

    // ---- epilogue: bias + relu + store ----
#pragma unroll
    for (int nt = 0; nt < 4; nt++) {
        int c = wn * 32 + nt * 8 + 2 * t;
        float b0 = __ldg(&bias[c]), b1 = __ldg(&bias[c + 1]);
#pragma unroll
        for (int mt = 0; mt < 4; mt++) {
            int m = m0 + wm * 64 + mt * 16 + g;
            if (m < n) {
                float2 o = make_float2(fmaxf(acc[mt][nt][0] + b0, 0.f),
                                       fmaxf(acc[mt][nt][1] + b1, 0.f));
                *(float2*)&out[(size_t)m * HH + c] = o;
            }
            if (m + 8 < n) {
                float2 o = make_float2(fmaxf(acc[mt][nt][2] + b0, 0.f),
                                       fmaxf(acc[mt][nt][3] + b1, 0.f));
                *(float2*)&out[(size_t)(m + 8) * HH + c] = o;
            }
        }
    }
}

// ------------------------------ pooling / head ------------------------------
__global__ void k_gbounds(const int* __restrict__ batch, int* gstart, int n, int g_num) {
    int g = blockIdx.x * blockDim.x + threadIdx.x;
    if (g > g_num) return;
    int lo = 0, hi = n;
    while (lo < hi) {
        int mid = (lo + hi) >> 1;
        if (batch[mid] < g) lo = mid + 1; else hi = mid;
    }
    gstart[g] = lo;
}

__global__ void k_pool(const float* __restrict__ x, const int* __restrict__ gstart,
                       float* __restrict__ pooled) {
    int g = blockIdx.x, t = threadIdx.x;
    int s = gstart[g], e = gstart[g + 1];
    float acc = 0.f;
    int r = s;
    for (; r + 4 <= e; r += 4) {
        acc += x[(size_t)(r + 0) * HH + t];
        acc += x[(size_t)(r + 1) * HH + t];
        acc += x[(size_t)(r + 2) * HH + t];
        acc += x[(size_t)(r + 3) * HH + t];
    }
    for (; r < e; r++) acc += x[(size_t)r * HH + t];
    float c = (float)(e - s);
    pooled[(size_t)g * HH + t] = acc / fmaxf(c, 1.0f);
}

__global__ void k_out(const float* __restrict__ pooled, const float* __restrict__ Wout,
                      const float* __restrict__ bout, float* __restrict__ out, int C) {
    __shared__ float pr[HH];
    int g = blockIdx.x, t = threadIdx.x;
    pr[t] = pooled[(size_t)g * HH + t];
    __syncthreads();
    if (t < C) {
        float s = bout[t];
#pragma unroll 8
        for (int k = 0; k < HH; k++) s += pr[k] * Wout[k * C + t];
        out[g * C + t] = s;
    }
}

// --------------------------------- launch -----------------------------------
extern "C" void kernel_launch(void* const* d_in, const int* in_sizes, int n_in,
                              void* d_out, int out_size) {
    const float* x     = (const float*)d_in[0];
    const int*   ei    = (const int*)d_in[1];
    const int*   batch = (const int*)d_in[2];
    int iw, ibs, iwo, ibo;
    if (n_in >= 8) { iw = 4; ibs = 5; iwo = 6; ibo = 7; }  // num_graphs at index 3
    else           { iw = 3; ibs = 4; iwo = 5; ibo = 6; }
    const float* Ws   = (const float*)d_in[iw];
    const float* bs   = (const float*)d_in[ibs];
    const float* Wout = (const float*)d_in[iwo];
    const float* bout = (const float*)d_in[ibo];

    int N = in_sizes[2];
    int E = in_sizes[1] / 2;
    int H = in_sizes[0] / N;            // expect 128
    int C = in_sizes[ibo];
    int L = in_sizes[ibs] / H;
    int G = out_size / C;
    if (N > MAXN || (E + N) > MAXT || G > MAXG || H != HH) return;

    void* p;
    cudaGetSymbolAddress(&p, g_cnt);     int*   cnt    = (int*)p;
    cudaGetSymbolAddress(&p, g_dis);     float* dis    = (float*)p;
    cudaGetSymbolAddress(&p, g_rowptr);  int*   rowptr = (int*)p;
    cudaGetSymbolAddress(&p, g_cursor);  int*   cursor = (int*)p;
    cudaGetSymbolAddress(&p, g_edges);   int2*  edges  = (int2*)p;
    cudaGetSymbolAddress(&p, g_agg);     float* agg    = (float*)p;
    cudaGetSymbolAddress(&p, g_x1);      float* x1     = (float*)p;
    cudaGetSymbolAddress(&p, g_x2);      float* x2     = (float*)p;
    cudaGetSymbolAddress(&p, g_bsum);    int*   bsum   = (int*)p;
    cudaGetSymbolAddress(&p, g_gstart);  int*   gstart = (int*)p;
    cudaGetSymbolAddress(&p, g_pooled);  float* pooled = (float*)p;

    cudaFuncSetAttribute(k_gemm_tc, cudaFuncAttributeMaxDynamicSharedMemorySize, SMEM_GEMM);

    const int* src = ei;
    const int* dst = ei + E;

    k_init <<<(N + 255) / 256, 256>>>(cnt, N);
    k_count<<<(E + 255) / 256, 256>>>(dst, cnt, E);
    k_dis  <<<(N + 255) / 256, 256>>>(cnt, dis, N);

    int NB = (N + 1023) / 1024;
    k_scan1<<<NB, 256>>>(cnt, bsum, N);
    k_scan2<<<1, 256>>>(bsum, rowptr, NB, N);
    k_scan3<<<NB, 256>>>(cnt, bsum, rowptr, cursor, N);
    k_fill <<<(E + N + 255) / 256, 256>>>(src, dst, dis, cursor, edges, E, N);

    const float* xin = x;
    for (int l = 0; l < L; l++) {
        k_spmm<<<(N + 7) / 8, 256>>>(rowptr, edges, xin, agg, N);
        float* xout = (l & 1) ? x2 : x1;
        k_gemm_tc<<<(N + 127) / 128, 256, SMEM_GEMM>>>(agg, Ws + (size_t)l * H * H,
                                                       bs + (size_t)l * H, xout, N);
        xin = xout;
    }

    k_gbounds<<<(G + 1 + 127) / 128, 128>>>(batch, gstart, N, G);
    k_pool<<<G, HH>>>(xin, gstart, pooled);
    k_out <<<G, HH>>>(pooled, Wout, bout, (float*)d_out, C);
}

// round 8
// speedup vs baseline: 1.5077x; 1.1298x over previous
#include <cuda_runtime.h>
#include <cuda_bf16.h>
#include <cstdint>

// ----------------------------------------------------------------------------
// GCN: 5x (GCNConv + ReLU) + global mean pool + linear head.
//   Fixed shapes: N=100000, E=1600000, H=128, C=10, L=5, G=64
//   - CSR build over dst (self-loops included), norm = dis[s]*dis[d]
//   - Per layer: agg = A_norm * x   (warp-per-row CSR SpMM, no atomics)
//                x   = relu(agg @ W + b)  via tensor-core tf32 mma with
//                3-term error-compensated split (hi=tf32, lo=bf16).
//                W fragments pre-split once per layer (k_prepw) -> GEMM blocks
//                read them straight from L1/L2, smem holds only A (96KB ->
//                2 blocks/SM, staging overlaps compute).
//   - Mean-pool per graph (batch sorted -> binary-search boundaries)
// ----------------------------------------------------------------------------

#define MAXN 100352
#define MAXT 1703936      // >= E + N
#define MAXG 1024
#define HH   128

__device__ int   g_cnt[MAXN];
__device__ float g_dis[MAXN];
__device__ int   g_rowptr[MAXN + 1];
__device__ int   g_cursor[MAXN];
__device__ int2  g_edges[MAXT];
__device__ float g_agg[(size_t)MAXN * HH];
__device__ float g_x1 [(size_t)MAXN * HH];
__device__ float g_x2 [(size_t)MAXN * HH];
__device__ int   g_bsum[256];
__device__ int   g_gstart[MAXG + 1];
__device__ float g_pooled[(size_t)MAXG * HH];
__device__ uint2    g_wh[8192];   // W tf32-hi fragments (per current layer)
__device__ uint32_t g_wl[8192];   // W bf16-lo fragments

// ------------------------------- graph prep ---------------------------------
__global__ void k_init(int* cnt, int n) {
    int i = blockIdx.x * blockDim.x + threadIdx.x;
    if (i < n) cnt[i] = 1;  // self loop
}

__global__ void k_count(const int* __restrict__ dst, int* cnt, int e) {
    int i = blockIdx.x * blockDim.x + threadIdx.x;
    if (i < e) atomicAdd(&cnt[dst[i]], 1);
}

__global__ void k_dis(const int* __restrict__ cnt, float* dis, int n) {
    int i = blockIdx.x * blockDim.x + threadIdx.x;
    if (i < n) dis[i] = rsqrtf((float)cnt[i]);  // cnt >= 1 always
}

__global__ void k_scan1(const int* __restrict__ cnt, int* bsum, int n) {
    __shared__ int sh[256];
    int t = threadIdx.x;
    int base = blockIdx.x * 1024 + t * 4;
    int s = 0;
#pragma unroll
    for (int i = 0; i < 4; i++)
        if (base + i < n) s += cnt[base + i];
    sh[t] = s;
    __syncthreads();
#pragma unroll
    for (int off = 128; off > 0; off >>= 1) {
        if (t < off) sh[t] += sh[t + off];
        __syncthreads();
    }
    if (t == 0) bsum[blockIdx.x] = sh[0];
}

__global__ void k_scan2(int* bsum, int* rowptr, int nb, int n) {
    __shared__ int sh[256];
    int t = threadIdx.x;
    sh[t] = (t < nb) ? bsum[t] : 0;
    __syncthreads();
    for (int off = 1; off < 256; off <<= 1) {
        int v = (t >= off) ? sh[t - off] : 0;
        __syncthreads();
        sh[t] += v;
        __syncthreads();
    }
    if (t < nb) bsum[t] = (t == 0) ? 0 : sh[t - 1];
    if (t == 0) rowptr[n] = sh[nb - 1];
}

__global__ void k_scan3(const int* __restrict__ cnt, const int* __restrict__ bsumex,
                        int* rowptr, int* cursor, int n) {
    __shared__ int sh[256];
    int t = threadIdx.x;
    int base = blockIdx.x * 1024 + t * 4;
    int v0 = 0, v1 = 0, v2 = 0, v3 = 0;
    if (base + 0 < n) v0 = cnt[base + 0];
    if (base + 1 < n) v1 = cnt[base + 1];
    if (base + 2 < n) v2 = cnt[base + 2];
    if (base + 3 < n) v3 = cnt[base + 3];
    int s = v0 + v1 + v2 + v3;
    sh[t] = s;
    __syncthreads();
    for (int off = 1; off < 256; off <<= 1) {
        int v = (t >= off) ? sh[t - off] : 0;
        __syncthreads();
        sh[t] += v;
        __syncthreads();
    }
    int ex = (t == 0) ? 0 : sh[t - 1];
    int off0 = bsumex[blockIdx.x] + ex;
    if (base + 0 < n) { rowptr[base + 0] = off0;                cursor[base + 0] = off0; }
    if (base + 1 < n) { rowptr[base + 1] = off0 + v0;           cursor[base + 1] = off0 + v0; }
    if (base + 2 < n) { rowptr[base + 2] = off0 + v0 + v1;      cursor[base + 2] = off0 + v0 + v1; }
    if (base + 3 < n) { rowptr[base + 3] = off0 + v0 + v1 + v2; cursor[base + 3] = off0 + v0 + v1 + v2; }
}

__global__ void k_fill(const int* __restrict__ src, const int* __restrict__ dst,
                       const float* __restrict__ dis, int* cursor, int2* edges,
                       int e, int n) {
    int i = blockIdx.x * blockDim.x + threadIdx.x;
    if (i >= e + n) return;
    int s, d;
    if (i < e) { s = src[i]; d = dst[i]; }
    else       { s = d = i - e; }
    float w = dis[s] * dis[d];
    int pos = atomicAdd(&cursor[d], 1);
    edges[pos] = make_int2(s, __float_as_int(w));
}

// --------------------------------- SpMM -------------------------------------
__global__ void k_spmm(const int* __restrict__ rowptr, const int2* __restrict__ edges,
                       const float* __restrict__ xin, float* __restrict__ xout, int n) {
    int row  = (blockIdx.x * blockDim.x + threadIdx.x) >> 5;
    int lane = threadIdx.x & 31;
    if (row >= n) return;
    int s = rowptr[row], e = rowptr[row + 1];
    const float4* x4 = (const float4*)xin;
    float4 acc = make_float4(0.f, 0.f, 0.f, 0.f);
    int j = s;
    for (; j + 4 <= e; j += 4) {
        int2 e0 = __ldg(&edges[j + 0]);
        int2 e1 = __ldg(&edges[j + 1]);
        int2 e2 = __ldg(&edges[j + 2]);
        int2 e3 = __ldg(&edges[j + 3]);
        float4 v0 = __ldg(&x4[(size_t)e0.x * 32 + lane]);
        float4 v1 = __ldg(&x4[(size_t)e1.x * 32 + lane]);
        float4 v2 = __ldg(&x4[(size_t)e2.x * 32 + lane]);
        float4 v3 = __ldg(&x4[(size_t)e3.x * 32 + lane]);
        float w0 = __int_as_float(e0.y), w1 = __int_as_float(e1.y);
        float w2 = __int_as_float(e2.y), w3 = __int_as_float(e3.y);
        acc.x += w0 * v0.x; acc.y += w0 * v0.y; acc.z += w0 * v0.z; acc.w += w0 * v0.w;
        acc.x += w1 * v1.x; acc.y += w1 * v1.y; acc.z += w1 * v1.z; acc.w += w1 * v1.w;
        acc.x += w2 * v2.x; acc.y += w2 * v2.y; acc.z += w2 * v2.z; acc.w += w2 * v2.w;
        acc.x += w3 * v3.x; acc.y += w3 * v3.y; acc.z += w3 * v3.z; acc.w += w3 * v3.w;
    }
    for (; j < e; j++) {
        int2 ed = __ldg(&edges[j]);
        float w = __int_as_float(ed.y);
        float4 v = __ldg(&x4[(size_t)ed.x * 32 + lane]);
        acc.x += w * v.x; acc.y += w * v.y; acc.z += w * v.z; acc.w += w * v.w;
    }
    ((float4*)xout)[(size_t)row * 32 + lane] = acc;
}

// ------------------------- tensor-core GEMM helpers --------------------------
__device__ __forceinline__ uint32_t f2tf32(float v) {
    uint32_t u;
    asm("cvt.rna.tf32.f32 %0, %1;" : "=r"(u) : "f"(v));
    return u;
}
// pack two residuals as bf16x2; e0 -> lower half, e1 -> upper half
__device__ __forceinline__ uint32_t packbf(float e0, float e1) {
    uint32_t r;
    asm("cvt.rn.bf16x2.f32 %0, %1, %2;" : "=r"(r) : "f"(e1), "f"(e0));
    return r;
}
__device__ __forceinline__ void mma8(float* c,
                                     uint32_t a0, uint32_t a1, uint32_t a2, uint32_t a3,
                                     uint32_t b0, uint32_t b1) {
    asm volatile(
        "mma.sync.aligned.m16n8k8.row.col.f32.tf32.tf32.f32 "
        "{%0,%1,%2,%3}, {%4,%5,%6,%7}, {%8,%9}, {%0,%1,%2,%3};"
        : "+f"(c[0]), "+f"(c[1]), "+f"(c[2]), "+f"(c[3])
        : "r"(a0), "r"(a1), "r"(a2), "r"(a3), "r"(b0), "r"(b1));
}

// --------------------- per-layer W fragment pre-split ------------------------
// slot = (ks*16 + nt)*32 + lane ; lane: g=lane>>2 (col within 8), t=lane&3 (k)
// wh[slot] = { tf32(W[ks*8+t][nt*8+g]), tf32(W[ks*8+t+4][nt*8+g]) }
// wl[slot] = bf16x2 of the residuals.
__global__ void k_prepw(const float* __restrict__ W, uint2* __restrict__ wh,
                        uint32_t* __restrict__ wl) {
    int idx = blockIdx.x * blockDim.x + threadIdx.x;   // 0..8191
    int lane = idx & 31, tile = idx >> 5;
    int nt = tile & 15, ks = tile >> 4;
    int t = lane & 3, g = lane >> 2;
    int row = ks * 8 + t, col = nt * 8 + g;
    float v0 = W[row * HH + col];
    float v1 = W[(row + 4) * HH + col];
    uint32_t h0 = f2tf32(v0), h1 = f2tf32(v1);
    float l0 = v0 - __uint_as_float(h0), l1 = v1 - __uint_as_float(h1);
    wh[idx] = make_uint2(h0, h1);
    wl[idx] = packbf(l0, l1);
}

// --------------------------------- GEMM --------------------------------------
// out[m][c] = relu( sum_k A[m][k]*W[k][c] + bias[c] ), block tile 128x128, K=128
// Shared holds ONLY the A fragments (96KB) -> 2 blocks/SM. W fragments come
// from the pre-split global arrays (L1-resident, coalesced LDG.64/LDG.32).
//   Ah: 16ks x 8mt x 32lane x uint4  (64KB)   tf32 hi parts of A
//   Al: same shape, uint2 bf16 residuals (32KB)
#define SMEM_GEMM 98304

__global__ __launch_bounds__(256)
void k_gemm_tc(const float* __restrict__ A,
               const uint2* __restrict__ wh, const uint32_t* __restrict__ wl,
               const float* __restrict__ bias, float* __restrict__ out, int n) {
    extern __shared__ char sh[];
    uint4* Ah = (uint4*)sh;                      // 4096 slots
    uint2* Al = (uint2*)(sh + 65536);            // 4096 slots

    const int tid  = threadIdx.x;
    const int lane = tid & 31;
    const int g = lane >> 2, t = lane & 3;
    const int m0 = blockIdx.x << 7;

    // ---- stage A fragments (each thread owns whole lane-slots -> vector STS) ----
#pragma unroll
    for (int i = 0; i < 16; i++) {
        int s    = tid + i * 256;      // slot id; (s & 31) == lane
        int tile = s >> 5;             // 0..127
        int mt = tile & 7, ks = tile >> 3;
        int mrow = m0 + mt * 16 + g;
        int col  = ks * 8 + t;
        float v0 = 0.f, v1 = 0.f, v2 = 0.f, v3 = 0.f;
        if (mrow < n) {
            v0 = __ldg(&A[(size_t)mrow * HH + col]);
            v2 = __ldg(&A[(size_t)mrow * HH + col + 4]);
        }
        if (mrow + 8 < n) {
            v1 = __ldg(&A[(size_t)(mrow + 8) * HH + col]);
            v3 = __ldg(&A[(size_t)(mrow + 8) * HH + col + 4]);
        }
        uint32_t h0 = f2tf32(v0), h1 = f2tf32(v1), h2 = f2tf32(v2), h3 = f2tf32(v3);
        float l0 = v0 - __uint_as_float(h0), l1 = v1 - __uint_as_float(h1);
        float l2 = v2 - __uint_as_float(h2), l3 = v3 - __uint_as_float(h3);
        Ah[s] = make_uint4(h0, h1, h2, h3);
        Al[s] = make_uint2(packbf(l0, l1), packbf(l2, l3));
    }
    __syncthreads();

    const int warp = tid >> 5;
    const int wm = warp >> 2;      // 0..1  (64 rows each)
    const int wn = warp & 3;       // 0..3  (32 cols each)

    float acc[4][4][4];
#pragma unroll
    for (int a = 0; a < 4; a++)
#pragma unroll
        for (int b = 0; b < 4; b++)
#pragma unroll
            for (int c = 0; c < 4; c++) acc[a][b][c] = 0.f;

#pragma unroll 2
    for (int ks = 0; ks < 16; ks++) {
        uint2 bh[4]; uint32_t blp[4];
#pragma unroll
        for (int nt = 0; nt < 4; nt++) {
            int slot = (ks * 16 + wn * 4 + nt) * 32 + lane;
            bh[nt]  = __ldg(&wh[slot]);
            blp[nt] = __ldg(&wl[slot]);
        }
        uint4 ah[4]; uint2 alp[4];
#pragma unroll
        for (int mt = 0; mt < 4; mt++) {
            int slot = (ks * 8 + wm * 4 + mt) * 32 + lane;
            ah[mt]  = Ah[slot];
            alp[mt] = Al[slot];
        }
#pragma unroll
        for (int mt = 0; mt < 4; mt++) {
            uint32_t a0 = ah[mt].x, a1 = ah[mt].y, a2 = ah[mt].z, a3 = ah[mt].w;
            uint32_t q0 = alp[mt].x << 16, q1 = alp[mt].x & 0xFFFF0000u;
            uint32_t q2 = alp[mt].y << 16, q3 = alp[mt].y & 0xFFFF0000u;
#pragma unroll
            for (int nt = 0; nt < 4; nt++) {
                uint32_t b0 = bh[nt].x, b1 = bh[nt].y;
                uint32_t r0 = blp[nt] << 16, r1 = blp[nt] & 0xFFFF0000u;
                mma8(acc[mt][nt], a0, a1, a2, a3, b0, b1);   // hi*hi
                mma8(acc[mt][nt], a0, a1, a2, a3, r0, r1);   // hi*lo
                mma8(acc[mt][nt], q0, q1, q2, q3, b0, b1);   // lo*hi
            }
        }
    }

    // ---- epilogue: bias + relu + store ----
#pragma unroll
    for (int nt = 0; nt < 4; nt++) {
        int c = wn * 32 + nt * 8 + 2 * t;
        float b0 = __ldg(&bias[c]), b1 = __ldg(&bias[c + 1]);
#pragma unroll
        for (int mt = 0; mt < 4; mt++) {
            int m = m0 + wm * 64 + mt * 16 + g;
            if (m < n) {
                float2 o = make_float2(fmaxf(acc[mt][nt][0] + b0, 0.f),
                                       fmaxf(acc[mt][nt][1] + b1, 0.f));
                *(float2*)&out[(size_t)m * HH + c] = o;
            }
            if (m + 8 < n) {
                float2 o = make_float2(fmaxf(acc[mt][nt][2] + b0, 0.f),
                                       fmaxf(acc[mt][nt][3] + b1, 0.f));
                *(float2*)&out[(size_t)(m + 8) * HH + c] = o;
            }
        }
    }
}

// ------------------------------ pooling / head ------------------------------
__global__ void k_gbounds(const int* __restrict__ batch, int* gstart, int n, int g_num) {
    int g = blockIdx.x * blockDim.x + threadIdx.x;
    if (g > g_num) return;
    int lo = 0, hi = n;
    while (lo < hi) {
        int mid = (lo + hi) >> 1;
        if (batch[mid] < g) lo = mid + 1; else hi = mid;
    }
    gstart[g] = lo;
}

__global__ void k_pool(const float* __restrict__ x, const int* __restrict__ gstart,
                       float* __restrict__ pooled) {
    int g = blockIdx.x, t = threadIdx.x;
    int s = gstart[g], e = gstart[g + 1];
    float acc = 0.f;
    int r = s;
    for (; r + 4 <= e; r += 4) {
        acc += x[(size_t)(r + 0) * HH + t];
        acc += x[(size_t)(r + 1) * HH + t];
        acc += x[(size_t)(r + 2) * HH + t];
        acc += x[(size_t)(r + 3) * HH + t];
    }
    for (; r < e; r++) acc += x[(size_t)r * HH + t];
    float c = (float)(e - s);
    pooled[(size_t)g * HH + t] = acc / fmaxf(c, 1.0f);
}

__global__ void k_out(const float* __restrict__ pooled, const float* __restrict__ Wout,
                      const float* __restrict__ bout, float* __restrict__ out, int C) {
    __shared__ float pr[HH];
    int g = blockIdx.x, t = threadIdx.x;
    pr[t] = pooled[(size_t)g * HH + t];
    __syncthreads();
    if (t < C) {
        float s = bout[t];
#pragma unroll 8
        for (int k = 0; k < HH; k++) s += pr[k] * Wout[k * C + t];
        out[g * C + t] = s;
    }
}

// --------------------------------- launch -----------------------------------
extern "C" void kernel_launch(void* const* d_in, const int* in_sizes, int n_in,
                              void* d_out, int out_size) {
    const float* x     = (const float*)d_in[0];
    const int*   ei    = (const int*)d_in[1];
    const int*   batch = (const int*)d_in[2];
    int iw, ibs, iwo, ibo;
    if (n_in >= 8) { iw = 4; ibs = 5; iwo = 6; ibo = 7; }  // num_graphs at index 3
    else           { iw = 3; ibs = 4; iwo = 5; ibo = 6; }
    const float* Ws   = (const float*)d_in[iw];
    const float* bs   = (const float*)d_in[ibs];
    const float* Wout = (const float*)d_in[iwo];
    const float* bout = (const float*)d_in[ibo];

    int N = in_sizes[2];
    int E = in_sizes[1] / 2;
    int H = in_sizes[0] / N;            // expect 128
    int C = in_sizes[ibo];
    int L = in_sizes[ibs] / H;
    int G = out_size / C;
    if (N > MAXN || (E + N) > MAXT || G > MAXG || H != HH) return;

    void* p;
    cudaGetSymbolAddress(&p, g_cnt);     int*   cnt    = (int*)p;
    cudaGetSymbolAddress(&p, g_dis);     float* dis    = (float*)p;
    cudaGetSymbolAddress(&p, g_rowptr);  int*   rowptr = (int*)p;
    cudaGetSymbolAddress(&p, g_cursor);  int*   cursor = (int*)p;
    cudaGetSymbolAddress(&p, g_edges);   int2*  edges  = (int2*)p;
    cudaGetSymbolAddress(&p, g_agg);     float* agg    = (float*)p;
    cudaGetSymbolAddress(&p, g_x1);      float* x1     = (float*)p;
    cudaGetSymbolAddress(&p, g_x2);      float* x2     = (float*)p;
    cudaGetSymbolAddress(&p, g_bsum);    int*   bsum   = (int*)p;
    cudaGetSymbolAddress(&p, g_gstart);  int*   gstart = (int*)p;
    cudaGetSymbolAddress(&p, g_pooled);  float* pooled = (float*)p;
    cudaGetSymbolAddress(&p, g_wh);      uint2* wh     = (uint2*)p;
    cudaGetSymbolAddress(&p, g_wl);      uint32_t* wl  = (uint32_t*)p;

    cudaFuncSetAttribute(k_gemm_tc, cudaFuncAttributeMaxDynamicSharedMemorySize, SMEM_GEMM);

    const int* src = ei;
    const int* dst = ei + E;

    k_init <<<(N + 255) / 256, 256>>>(cnt, N);
    k_count<<<(E + 255) / 256, 256>>>(dst, cnt, E);
    k_dis  <<<(N + 255) / 256, 256>>>(cnt, dis, N);

    int NB = (N + 1023) / 1024;
    k_scan1<<<NB, 256>>>(cnt, bsum, N);
    k_scan2<<<1, 256>>>(bsum, rowptr, NB, N);
    k_scan3<<<NB, 256>>>(cnt, bsum, rowptr, cursor, N);
    k_fill <<<(E + N + 255) / 256, 256>>>(src, dst, dis, cursor, edges, E, N);

    const float* xin = x;
    for (int l = 0; l < L; l++) {
        k_spmm<<<(N + 7) / 8, 256>>>(rowptr, edges, xin, agg, N);
        k_prepw<<<32, 256>>>(Ws + (size_t)l * H * H, wh, wl);
        float* xout = (l & 1) ? x2 : x1;
        k_gemm_tc<<<(N + 127) / 128, 256, SMEM_GEMM>>>(agg, wh, wl,
                                                       bs + (size_t)l * H, xout, N);
        xin = xout;
    }

    k_gbounds<<<(G + 1 + 127) / 128, 128>>>(batch, gstart, N, G);
    k_pool<<<G, HH>>>(xin, gstart, pooled);
    k_out <<<G, HH>>>(pooled, Wout, bout, (float*)d_out, C);
}

// round 9
// speedup vs baseline: 1.6413x; 1.0886x over previous
#include <cuda_runtime.h>
#include <cuda_bf16.h>
#include <cstdint>

// ----------------------------------------------------------------------------
// GCN: 5x (GCNConv + ReLU) + global mean pool + linear head.
//   Fixed shapes: N=100000, E=1600000, H=128, C=10, L=5, G=64
//   - CSR build over dst (self-loops included), norm = dis[s]*dis[d]
//   - Per layer: agg = A_norm * x   (warp-per-row CSR SpMM, no atomics)
//                x   = relu(agg @ W + b)  via tensor-core tf32 mma with
//                3-term error-compensated split (hi=tf32, lo=bf16).
//                All layers' W fragments pre-split in ONE upfront kernel.
//   - Chunked mean-pool (sorted batch -> per-chunk partial sums + atomics)
// ----------------------------------------------------------------------------

#define MAXN 100352
#define MAXT 1703936      // >= E + N
#define MAXG 1024
#define MAXL 8
#define HH   128

__device__ int   g_cnt[MAXN];
__device__ float g_dis[MAXN];
__device__ int   g_rowptr[MAXN + 1];
__device__ int   g_cursor[MAXN];
__device__ int2  g_edges[MAXT];
__device__ float g_agg[(size_t)MAXN * HH];
__device__ float g_x1 [(size_t)MAXN * HH];
__device__ float g_x2 [(size_t)MAXN * HH];
__device__ int   g_bsum[256];
__device__ int   g_gstart[MAXG + 1];
__device__ float g_psum[(size_t)MAXG * HH];
__device__ uint2    g_wh[MAXL * 8192];   // W tf32-hi fragments (all layers)
__device__ uint32_t g_wl[MAXL * 8192];   // W bf16-lo fragments

// ------------------------------- graph prep ---------------------------------
__global__ void k_init(int* cnt, int n) {
    int i = blockIdx.x * blockDim.x + threadIdx.x;
    if (i < n) cnt[i] = 1;  // self loop
}

__global__ void k_count(const int* __restrict__ dst, int* cnt, int e) {
    int i = blockIdx.x * blockDim.x + threadIdx.x;
    if (i < e) atomicAdd(&cnt[dst[i]], 1);
}

// partial block sums for exclusive scan; also emits dis = rsqrt(cnt)
__global__ void k_scan1(const int* __restrict__ cnt, int* bsum, float* dis, int n) {
    __shared__ int sh[256];
    int t = threadIdx.x;
    int base = blockIdx.x * 1024 + t * 4;
    int s = 0;
#pragma unroll
    for (int i = 0; i < 4; i++)
        if (base + i < n) {
            int c = cnt[base + i];
            s += c;
            dis[base + i] = rsqrtf((float)c);   // cnt >= 1 always
        }
    sh[t] = s;
    __syncthreads();
#pragma unroll
    for (int off = 128; off > 0; off >>= 1) {
        if (t < off) sh[t] += sh[t + off];
        __syncthreads();
    }
    if (t == 0) bsum[blockIdx.x] = sh[0];
}

__global__ void k_scan2(int* bsum, int* rowptr, int nb, int n) {
    __shared__ int sh[256];
    int t = threadIdx.x;
    sh[t] = (t < nb) ? bsum[t] : 0;
    __syncthreads();
    for (int off = 1; off < 256; off <<= 1) {
        int v = (t >= off) ? sh[t - off] : 0;
        __syncthreads();
        sh[t] += v;
        __syncthreads();
    }
    if (t < nb) bsum[t] = (t == 0) ? 0 : sh[t - 1];
    if (t == 0) rowptr[n] = sh[nb - 1];
}

__global__ void k_scan3(const int* __restrict__ cnt, const int* __restrict__ bsumex,
                        int* rowptr, int* cursor, int n) {
    __shared__ int sh[256];
    int t = threadIdx.x;
    int base = blockIdx.x * 1024 + t * 4;
    int v0 = 0, v1 = 0, v2 = 0, v3 = 0;
    if (base + 0 < n) v0 = cnt[base + 0];
    if (base + 1 < n) v1 = cnt[base + 1];
    if (base + 2 < n) v2 = cnt[base + 2];
    if (base + 3 < n) v3 = cnt[base + 3];
    int s = v0 + v1 + v2 + v3;
    sh[t] = s;
    __syncthreads();
    for (int off = 1; off < 256; off <<= 1) {
        int v = (t >= off) ? sh[t - off] : 0;
        __syncthreads();
        sh[t] += v;
        __syncthreads();
    }
    int ex = (t == 0) ? 0 : sh[t - 1];
    int off0 = bsumex[blockIdx.x] + ex;
    if (base + 0 < n) { rowptr[base + 0] = off0;                cursor[base + 0] = off0; }
    if (base + 1 < n) { rowptr[base + 1] = off0 + v0;           cursor[base + 1] = off0 + v0; }
    if (base + 2 < n) { rowptr[base + 2] = off0 + v0 + v1;      cursor[base + 2] = off0 + v0 + v1; }
    if (base + 3 < n) { rowptr[base + 3] = off0 + v0 + v1 + v2; cursor[base + 3] = off0 + v0 + v1 + v2; }
}

__global__ void k_fill(const int* __restrict__ src, const int* __restrict__ dst,
                       const float* __restrict__ dis, int* cursor, int2* edges,
                       int e, int n) {
    int i = blockIdx.x * blockDim.x + threadIdx.x;
    if (i >= e + n) return;
    int s, d;
    if (i < e) { s = src[i]; d = dst[i]; }
    else       { s = d = i - e; }
    float w = dis[s] * dis[d];
    int pos = atomicAdd(&cursor[d], 1);
    edges[pos] = make_int2(s, __float_as_int(w));
}

// --------------------------------- SpMM -------------------------------------
__global__ void k_spmm(const int* __restrict__ rowptr, const int2* __restrict__ edges,
                       const float* __restrict__ xin, float* __restrict__ xout, int n) {
    int row  = (blockIdx.x * blockDim.x + threadIdx.x) >> 5;
    int lane = threadIdx.x & 31;
    if (row >= n) return;
    int s = rowptr[row], e = rowptr[row + 1];
    const float4* x4 = (const float4*)xin;
    float4 acc = make_float4(0.f, 0.f, 0.f, 0.f);
    int j = s;
    for (; j + 4 <= e; j += 4) {
        int2 e0 = __ldg(&edges[j + 0]);
        int2 e1 = __ldg(&edges[j + 1]);
        int2 e2 = __ldg(&edges[j + 2]);
        int2 e3 = __ldg(&edges[j + 3]);
        float4 v0 = __ldg(&x4[(size_t)e0.x * 32 + lane]);
        float4 v1 = __ldg(&x4[(size_t)e1.x * 32 + lane]);
        float4 v2 = __ldg(&x4[(size_t)e2.x * 32 + lane]);
        float4 v3 = __ldg(&x4[(size_t)e3.x * 32 + lane]);
        float w0 = __int_as_float(e0.y), w1 = __int_as_float(e1.y);
        float w2 = __int_as_float(e2.y), w3 = __int_as_float(e3.y);
        acc.x += w0 * v0.x; acc.y += w0 * v0.y; acc.z += w0 * v0.z; acc.w += w0 * v0.w;
        acc.x += w1 * v1.x; acc.y += w1 * v1.y; acc.z += w1 * v1.z; acc.w += w1 * v1.w;
        acc.x += w2 * v2.x; acc.y += w2 * v2.y; acc.z += w2 * v2.z; acc.w += w2 * v2.w;
        acc.x += w3 * v3.x; acc.y += w3 * v3.y; acc.z += w3 * v3.z; acc.w += w3 * v3.w;
    }
    for (; j < e; j++) {
        int2 ed = __ldg(&edges[j]);
        float w = __int_as_float(ed.y);
        float4 v = __ldg(&x4[(size_t)ed.x * 32 + lane]);
        acc.x += w * v.x; acc.y += w * v.y; acc.z += w * v.z; acc.w += w * v.w;
    }
    ((float4*)xout)[(size_t)row * 32 + lane] = acc;
}

// ------------------------- tensor-core GEMM helpers --------------------------
__device__ __forceinline__ uint32_t f2tf32(float v) {
    uint32_t u;
    asm("cvt.rna.tf32.f32 %0, %1;" : "=r"(u) : "f"(v));
    return u;
}
// pack two residuals as bf16x2; e0 -> lower half, e1 -> upper half
__device__ __forceinline__ uint32_t packbf(float e0, float e1) {
    uint32_t r;
    asm("cvt.rn.bf16x2.f32 %0, %1, %2;" : "=r"(r) : "f"(e1), "f"(e0));
    return r;
}
__device__ __forceinline__ void mma8(float* c,
                                     uint32_t a0, uint32_t a1, uint32_t a2, uint32_t a3,
                                     uint32_t b0, uint32_t b1) {
    asm volatile(
        "mma.sync.aligned.m16n8k8.row.col.f32.tf32.tf32.f32 "
        "{%0,%1,%2,%3}, {%4,%5,%6,%7}, {%8,%9}, {%0,%1,%2,%3};"
        : "+f"(c[0]), "+f"(c[1]), "+f"(c[2]), "+f"(c[3])
        : "r"(a0), "r"(a1), "r"(a2), "r"(a3), "r"(b0), "r"(b1));
}

// ----------------- per-layer W fragment pre-split (ALL layers) ---------------
// layer = blockIdx.x >> 5; within layer: slot = (ks*16 + nt)*32 + lane
// wh[slot] = { tf32(W[ks*8+t][nt*8+g]), tf32(W[ks*8+t+4][nt*8+g]) }
// wl[slot] = bf16x2 of the residuals.
__global__ void k_prepw_all(const float* __restrict__ Ws, uint2* __restrict__ wh,
                            uint32_t* __restrict__ wl) {
    int l = blockIdx.x >> 5;
    int idx = (blockIdx.x & 31) * 256 + threadIdx.x;   // 0..8191
    const float* W = Ws + (size_t)l * HH * HH;
    int lane = idx & 31, tile = idx >> 5;
    int nt = tile & 15, ks = tile >> 4;
    int t = lane & 3, g = lane >> 2;
    int row = ks * 8 + t, col = nt * 8 + g;
    float v0 = W[row * HH + col];
    float v1 = W[(row + 4) * HH + col];
    uint32_t h0 = f2tf32(v0), h1 = f2tf32(v1);
    float l0 = v0 - __uint_as_float(h0), l1 = v1 - __uint_as_float(h1);
    wh[l * 8192 + idx] = make_uint2(h0, h1);
    wl[l * 8192 + idx] = packbf(l0, l1);
}

// --------------------------------- GEMM --------------------------------------
// out[m][c] = relu( sum_k A[m][k]*W[k][c] + bias[c] ), block tile 128x128, K=128
// Shared holds ONLY the A fragments (96KB) -> 2 blocks/SM. W fragments come
// from the pre-split global arrays (L1-resident, coalesced LDG.64/LDG.32).
#define SMEM_GEMM 98304

__global__ __launch_bounds__(256)
void k_gemm_tc(const float* __restrict__ A,
               const uint2* __restrict__ wh, const uint32_t* __restrict__ wl,
               const float* __restrict__ bias, float* __restrict__ out, int n) {
    extern __shared__ char sh[];
    uint4* Ah = (uint4*)sh;                      // 4096 slots
    uint2* Al = (uint2*)(sh + 65536);            // 4096 slots

    const int tid  = threadIdx.x;
    const int lane = tid & 31;
    const int g = lane >> 2, t = lane & 3;
    const int m0 = blockIdx.x << 7;

    // ---- stage A fragments (each thread owns whole lane-slots -> vector STS) ----
#pragma unroll
    for (int i = 0; i < 16; i++) {
        int s    = tid + i * 256;      // slot id; (s & 31) == lane
        int tile = s >> 5;             // 0..127
        int mt = tile & 7, ks = tile >> 3;
        int mrow = m0 + mt * 16 + g;
        int col  = ks * 8 + t;
        float v0 = 0.f, v1 = 0.f, v2 = 0.f, v3 = 0.f;
        if (mrow < n) {
            v0 = __ldg(&A[(size_t)mrow * HH + col]);
            v2 = __ldg(&A[(size_t)mrow * HH + col + 4]);
        }
        if (mrow + 8 < n) {
            v1 = __ldg(&A[(size_t)(mrow + 8) * HH + col]);
            v3 = __ldg(&A[(size_t)(mrow + 8) * HH + col + 4]);
        }
        uint32_t h0 = f2tf32(v0), h1 = f2tf32(v1), h2 = f2tf32(v2), h3 = f2tf32(v3);
        float l0 = v0 - __uint_as_float(h0), l1 = v1 - __uint_as_float(h1);
        float l2 = v2 - __uint_as_float(h2), l3 = v3 - __uint_as_float(h3);
        Ah[s] = make_uint4(h0, h1, h2, h3);
        Al[s] = make_uint2(packbf(l0, l1), packbf(l2, l3));
    }
    __syncthreads();

    const int warp = tid >> 5;
    const int wm = warp >> 2;      // 0..1  (64 rows each)
    const int wn = warp & 3;       // 0..3  (32 cols each)

    float acc[4][4][4];
#pragma unroll
    for (int a = 0; a < 4; a++)
#pragma unroll
        for (int b = 0; b < 4; b++)
#pragma unroll
            for (int c = 0; c < 4; c++) acc[a][b][c] = 0.f;

#pragma unroll 2
    for (int ks = 0; ks < 16; ks++) {
        uint2 bh[4]; uint32_t blp[4];
#pragma unroll
        for (int nt = 0; nt < 4; nt++) {
            int slot = (ks * 16 + wn * 4 + nt) * 32 + lane;
            bh[nt]  = __ldg(&wh[slot]);
            blp[nt] = __ldg(&wl[slot]);
        }
        uint4 ah[4]; uint2 alp[4];
#pragma unroll
        for (int mt = 0; mt < 4; mt++) {
            int slot = (ks * 8 + wm * 4 + mt) * 32 + lane;
            ah[mt]  = Ah[slot];
            alp[mt] = Al[slot];
        }
#pragma unroll
        for (int mt = 0; mt < 4; mt++) {
            uint32_t a0 = ah[mt].x, a1 = ah[mt].y, a2 = ah[mt].z, a3 = ah[mt].w;
            uint32_t q0 = alp[mt].x << 16, q1 = alp[mt].x & 0xFFFF0000u;
            uint32_t q2 = alp[mt].y << 16, q3 = alp[mt].y & 0xFFFF0000u;
#pragma unroll
            for (int nt = 0; nt < 4; nt++) {
                uint32_t b0 = bh[nt].x, b1 = bh[nt].y;
                uint32_t r0 = blp[nt] << 16, r1 = blp[nt] & 0xFFFF0000u;
                mma8(acc[mt][nt], a0, a1, a2, a3, b0, b1);   // hi*hi
                mma8(acc[mt][nt], a0, a1, a2, a3, r0, r1);   // hi*lo
                mma8(acc[mt][nt], q0, q1, q2, q3, b0, b1);   // lo*hi
            }
        }
    }

    // ---- epilogue: bias + relu + store ----
#pragma unroll
    for (int nt = 0; nt < 4; nt++) {
        int c = wn * 32 + nt * 8 + 2 * t;
        float b0 = __ldg(&bias[c]), b1 = __ldg(&bias[c + 1]);
#pragma unroll
        for (int mt = 0; mt < 4; mt++) {
            int m = m0 + wm * 64 + mt * 16 + g;
            if (m < n) {
                float2 o = make_float2(fmaxf(acc[mt][nt][0] + b0, 0.f),
                                       fmaxf(acc[mt][nt][1] + b1, 0.f));
                *(float2*)&out[(size_t)m * HH + c] = o;
            }
            if (m + 8 < n) {
                float2 o = make_float2(fmaxf(acc[mt][nt][2] + b0, 0.f),
                                       fmaxf(acc[mt][nt][3] + b1, 0.f));
                *(float2*)&out[(size_t)(m + 8) * HH + c] = o;
            }
        }
    }
}

// ------------------------------ pooling / head ------------------------------
// graph boundaries (binary search in sorted batch) + zero the pooled accumulator
__global__ void k_gbz(const int* __restrict__ batch, int* gstart, float* psum,
                      int n, int g_num) {
    int i = blockIdx.x * blockDim.x + threadIdx.x;
    if (i < g_num * HH) psum[i] = 0.f;
    if (i <= g_num) {
        int lo = 0, hi = n;
        while (lo < hi) {
            int mid = (lo + hi) >> 1;
            if (batch[mid] < i) lo = mid + 1; else hi = mid;
        }
        gstart[i] = lo;
    }
}

// chunked per-graph partial sums: block = 256-row chunk, thread = column
__global__ __launch_bounds__(128)
void k_psum(const float* __restrict__ x, const int* __restrict__ batch,
            float* __restrict__ psum, int n) {
    __shared__ int bsh[256];
    const int t = threadIdx.x;            // column 0..127
    const int r0 = blockIdx.x * 256;
    const int len = min(256, n - r0);
    for (int i = t; i < len; i += 128) bsh[i] = batch[r0 + i];
    __syncthreads();

    if (bsh[0] == bsh[len - 1]) {
        // fast path: whole chunk in one graph -> deep-MLP reduction
        float acc = 0.f;
        int i = 0;
        for (; i + 8 <= len; i += 8) {
            float v0 = x[(size_t)(r0 + i + 0) * HH + t];
            float v1 = x[(size_t)(r0 + i + 1) * HH + t];
            float v2 = x[(size_t)(r0 + i + 2) * HH + t];
            float v3 = x[(size_t)(r0 + i + 3) * HH + t];
            float v4 = x[(size_t)(r0 + i + 4) * HH + t];
            float v5 = x[(size_t)(r0 + i + 5) * HH + t];
            float v6 = x[(size_t)(r0 + i + 6) * HH + t];
            float v7 = x[(size_t)(r0 + i + 7) * HH + t];
            acc += ((v0 + v1) + (v2 + v3)) + ((v4 + v5) + (v6 + v7));
        }
        for (; i < len; i++) acc += x[(size_t)(r0 + i) * HH + t];
        atomicAdd(&psum[(size_t)bsh[0] * HH + t], acc);
    } else {
        float acc = 0.f;
        int curg = bsh[0];
        int i = 0;
        for (; i + 4 <= len; i += 4) {
            float v0 = x[(size_t)(r0 + i + 0) * HH + t];
            float v1 = x[(size_t)(r0 + i + 1) * HH + t];
            float v2 = x[(size_t)(r0 + i + 2) * HH + t];
            float v3 = x[(size_t)(r0 + i + 3) * HH + t];
            int g0 = bsh[i], g1 = bsh[i + 1], g2 = bsh[i + 2], g3 = bsh[i + 3];
            if (g0 != curg) { atomicAdd(&psum[(size_t)curg * HH + t], acc); acc = 0.f; curg = g0; }
            acc += v0;
            if (g1 != curg) { atomicAdd(&psum[(size_t)curg * HH + t], acc); acc = 0.f; curg = g1; }
            acc += v1;
            if (g2 != curg) { atomicAdd(&psum[(size_t)curg * HH + t], acc); acc = 0.f; curg = g2; }
            acc += v2;
            if (g3 != curg) { atomicAdd(&psum[(size_t)curg * HH + t], acc); acc = 0.f; curg = g3; }
            acc += v3;
        }
        for (; i < len; i++) {
            int g = bsh[i];
            if (g != curg) { atomicAdd(&psum[(size_t)curg * HH + t], acc); acc = 0.f; curg = g; }
            acc += x[(size_t)(r0 + i) * HH + t];
        }
        atomicAdd(&psum[(size_t)curg * HH + t], acc);
    }
}

// head: pooled = psum/cnt ; out = pooled @ W_out + b_out
__global__ void k_out(const float* __restrict__ psum, const int* __restrict__ gstart,
                      const float* __restrict__ Wout, const float* __restrict__ bout,
                      float* __restrict__ out, int C) {
    __shared__ float pr[HH];
    int g = blockIdx.x, t = threadIdx.x;
    float cntf = (float)(gstart[g + 1] - gstart[g]);
    float inv = 1.0f / fmaxf(cntf, 1.0f);
    pr[t] = psum[(size_t)g * HH + t] * inv;
    __syncthreads();
    if (t < C) {
        float s = bout[t];
#pragma unroll 8
        for (int k = 0; k < HH; k++) s += pr[k] * Wout[k * C + t];
        out[g * C + t] = s;
    }
}

// --------------------------------- launch -----------------------------------
extern "C" void kernel_launch(void* const* d_in, const int* in_sizes, int n_in,
                              void* d_out, int out_size) {
    const float* x     = (const float*)d_in[0];
    const int*   ei    = (const int*)d_in[1];
    const int*   batch = (const int*)d_in[2];
    int iw, ibs, iwo, ibo;
    if (n_in >= 8) { iw = 4; ibs = 5; iwo = 6; ibo = 7; }  // num_graphs at index 3
    else           { iw = 3; ibs = 4; iwo = 5; ibo = 6; }
    const float* Ws   = (const float*)d_in[iw];
    const float* bs   = (const float*)d_in[ibs];
    const float* Wout = (const float*)d_in[iwo];
    const float* bout = (const float*)d_in[ibo];

    int N = in_sizes[2];
    int E = in_sizes[1] / 2;
    int H = in_sizes[0] / N;            // expect 128
    int C = in_sizes[ibo];
    int L = in_sizes[ibs] / H;
    int G = out_size / C;
    if (N > MAXN || (E + N) > MAXT || G > MAXG || H != HH || L > MAXL) return;

    void* p;
    cudaGetSymbolAddress(&p, g_cnt);     int*   cnt    = (int*)p;
    cudaGetSymbolAddress(&p, g_dis);     float* dis    = (float*)p;
    cudaGetSymbolAddress(&p, g_rowptr);  int*   rowptr = (int*)p;
    cudaGetSymbolAddress(&p, g_cursor);  int*   cursor = (int*)p;
    cudaGetSymbolAddress(&p, g_edges);   int2*  edges  = (int2*)p;
    cudaGetSymbolAddress(&p, g_agg);     float* agg    = (float*)p;
    cudaGetSymbolAddress(&p, g_x1);      float* x1     = (float*)p;
    cudaGetSymbolAddress(&p, g_x2);      float* x2     = (float*)p;
    cudaGetSymbolAddress(&p, g_bsum);    int*   bsum   = (int*)p;
    cudaGetSymbolAddress(&p, g_gstart);  int*   gstart = (int*)p;
    cudaGetSymbolAddress(&p, g_psum);    float* psum   = (float*)p;
    cudaGetSymbolAddress(&p, g_wh);      uint2* wh     = (uint2*)p;
    cudaGetSymbolAddress(&p, g_wl);      uint32_t* wl  = (uint32_t*)p;

    cudaFuncSetAttribute(k_gemm_tc, cudaFuncAttributeMaxDynamicSharedMemorySize, SMEM_GEMM);

    const int* src = ei;
    const int* dst = ei + E;

    // W fragment pre-split for all layers (off the per-layer critical path)
    k_prepw_all<<<32 * L, 256>>>(Ws, wh, wl);
    // graph boundaries + zero pooled accumulator (independent of layers)
    k_gbz<<<(G * HH + 255) / 256, 256>>>(batch, gstart, psum, N, G);

    k_init <<<(N + 255) / 256, 256>>>(cnt, N);
    k_count<<<(E + 255) / 256, 256>>>(dst, cnt, E);

    int NB = (N + 1023) / 1024;
    k_scan1<<<NB, 256>>>(cnt, bsum, dis, N);
    k_scan2<<<1, 256>>>(bsum, rowptr, NB, N);
    k_scan3<<<NB, 256>>>(cnt, bsum, rowptr, cursor, N);
    k_fill <<<(E + N + 255) / 256, 256>>>(src, dst, dis, cursor, edges, E, N);

    const float* xin = x;
    for (int l = 0; l < L; l++) {
        k_spmm<<<(N + 7) / 8, 256>>>(rowptr, edges, xin, agg, N);
        float* xout = (l & 1) ? x2 : x1;
        k_gemm_tc<<<(N + 127) / 128, 256, SMEM_GEMM>>>(agg, wh + (size_t)l * 8192,
                                                       wl + (size_t)l * 8192,
                                                       bs + (size_t)l * H, xout, N);
        xin = xout;
    }

    k_psum<<<(N + 255) / 256, 128>>>(xin, batch, psum, N);
    k_out <<<G, HH>>>(psum, gstart, Wout, bout, (float*)d_out, C);
}